// round 3
// baseline (speedup 1.0000x reference)
#include <cuda_runtime.h>
#include <math.h>

// Problem constants
#define BS      2048
#define NE      64
#define NQ      16
#define IN_DIM  512
#define EMBED   512
#define OUT_DIM 512
#define NHEAD   8
#define HD      64

// Scratch (static __device__ arrays — allocation-free per harness rules)
__device__ float g_q [BS * NQ * EMBED];          //  64 MB  Q  (rows n<16 only)
__device__ float g_kv[(size_t)BS * NE * 1024];   // 512 MB  K|V interleaved per row (ldc=1024)
__device__ float g_a [BS * NQ * EMBED];          //  64 MB  attention output

__device__ __forceinline__ float neg_inf() { return __int_as_float(0xff800000u); }

// ---------------------------------------------------------------------------
// Generic 128x128x16 fp32 SGEMM:  C[m,n] = sum_d A[m,d] * B[n,d]
// MODE 0: KV projection   A=entities (direct rows), C=g_kv (ldc=1024)
// MODE 1: Q projection    A=entities (gathered rows n<16), C=g_q (ldc=512)
// MODE 2: out projection  A=g_a, C=d_out (ldc=512), +bias, post_mask zeroing
// Masks arrive as 32-bit words (bool uploaded as int32/float32): nonzero = set.
// ---------------------------------------------------------------------------
template <int MODE>
__global__ void __launch_bounds__(256)
sgemm_kernel(const float* __restrict__ Ain,
             const float* __restrict__ B,
             float* __restrict__ Cout,
             const float* __restrict__ bias,
             const unsigned int* __restrict__ mask)
{
    const float* A = (MODE == 2) ? (const float*)g_a : Ain;
    float*       C = (MODE == 0) ? g_kv : (MODE == 1) ? g_q : Cout;
    const int  ldc = (MODE == 0) ? 1024 : 512;

    __shared__ float As[16][128];
    __shared__ float Bs[16][128];

    const int tid  = threadIdx.x;
    const int tx   = tid & 15;        // 0..15 -> N microtile
    const int ty   = tid >> 4;        // 0..15 -> M microtile
    const int row0 = blockIdx.y * 128;
    const int col0 = blockIdx.x * 128;

    float acc[8][8];
#pragma unroll
    for (int i = 0; i < 8; i++)
#pragma unroll
        for (int j = 0; j < 8; j++) acc[i][j] = 0.0f;

    // Load mapping: 512 float4 per operand tile; thread handles rows sr, sr+64
    const int sr  = tid >> 2;            // 0..63
    const int c4  = (tid & 3) * 4;       // k-offset within 16

    int lr0 = row0 + sr;
    int lr1 = row0 + sr + 64;
    int ar0, ar1;
    if (MODE == 1) {                     // gather q-rows: qrow -> b*64 + (qrow&15)
        ar0 = ((lr0 >> 4) << 6) + (lr0 & 15);
        ar1 = ((lr1 >> 4) << 6) + (lr1 & 15);
    } else {
        ar0 = lr0; ar1 = lr1;
    }
    const int br0 = col0 + sr;
    const int br1 = col0 + sr + 64;

    const float* Ap0 = A + (size_t)ar0 * 512 + c4;
    const float* Ap1 = A + (size_t)ar1 * 512 + c4;
    const float* Bp0 = B + (size_t)br0 * 512 + c4;
    const float* Bp1 = B + (size_t)br1 * 512 + c4;

    for (int k0 = 0; k0 < 512; k0 += 16) {
        const float4 a0 = *(const float4*)(Ap0 + k0);
        const float4 a1 = *(const float4*)(Ap1 + k0);
        const float4 b0 = *(const float4*)(Bp0 + k0);
        const float4 b1 = *(const float4*)(Bp1 + k0);

        __syncthreads();
        As[c4 + 0][sr] = a0.x; As[c4 + 1][sr] = a0.y;
        As[c4 + 2][sr] = a0.z; As[c4 + 3][sr] = a0.w;
        As[c4 + 0][sr + 64] = a1.x; As[c4 + 1][sr + 64] = a1.y;
        As[c4 + 2][sr + 64] = a1.z; As[c4 + 3][sr + 64] = a1.w;
        Bs[c4 + 0][sr] = b0.x; Bs[c4 + 1][sr] = b0.y;
        Bs[c4 + 2][sr] = b0.z; Bs[c4 + 3][sr] = b0.w;
        Bs[c4 + 0][sr + 64] = b1.x; Bs[c4 + 1][sr + 64] = b1.y;
        Bs[c4 + 2][sr + 64] = b1.z; Bs[c4 + 3][sr + 64] = b1.w;
        __syncthreads();

#pragma unroll
        for (int kk = 0; kk < 16; kk++) {
            float av[8], bv[8];
            float4 t;
            t = *(const float4*)&As[kk][ty * 8];     av[0]=t.x; av[1]=t.y; av[2]=t.z; av[3]=t.w;
            t = *(const float4*)&As[kk][ty * 8 + 4]; av[4]=t.x; av[5]=t.y; av[6]=t.z; av[7]=t.w;
            t = *(const float4*)&Bs[kk][tx * 8];     bv[0]=t.x; bv[1]=t.y; bv[2]=t.z; bv[3]=t.w;
            t = *(const float4*)&Bs[kk][tx * 8 + 4]; bv[4]=t.x; bv[5]=t.y; bv[6]=t.z; bv[7]=t.w;
#pragma unroll
            for (int i = 0; i < 8; i++)
#pragma unroll
                for (int j = 0; j < 8; j++)
                    acc[i][j] = fmaf(av[i], bv[j], acc[i][j]);
        }
    }

    // Epilogue
#pragma unroll
    for (int i = 0; i < 8; i++) {
        const int grow = row0 + ty * 8 + i;
        if (MODE == 2) {
            const bool z = (mask[grow] != 0u);       // post_mask word (int32/float32 bool)
#pragma unroll
            for (int jj = 0; jj < 2; jj++) {
                const int col = col0 + tx * 8 + jj * 4;
                float4 r;
                r.x = z ? 0.0f : acc[i][jj * 4 + 0] + bias[col + 0];
                r.y = z ? 0.0f : acc[i][jj * 4 + 1] + bias[col + 1];
                r.z = z ? 0.0f : acc[i][jj * 4 + 2] + bias[col + 2];
                r.w = z ? 0.0f : acc[i][jj * 4 + 3] + bias[col + 3];
                *(float4*)(C + (size_t)grow * 512 + col) = r;
            }
        } else {
            const int col = col0 + tx * 8;
            *(float4*)(C + (size_t)grow * ldc + col) =
                make_float4(acc[i][0], acc[i][1], acc[i][2], acc[i][3]);
            *(float4*)(C + (size_t)grow * ldc + col + 4) =
                make_float4(acc[i][4], acc[i][5], acc[i][6], acc[i][7]);
        }
    }
}

// ---------------------------------------------------------------------------
// Attention: one block per (batch, head). 128 threads.
// logits = QK^T/8 with pre_mask -> -inf; softmax; NaN(all-masked) -> 0; AV.
// ---------------------------------------------------------------------------
__global__ void __launch_bounds__(128)
attn_kernel(const unsigned int* __restrict__ pre_mask)
{
    __shared__ float qs[16][68];   // pad 68: float4-aligned, conflict-free
    __shared__ float ks[64][68];
    __shared__ float vs[64][68];
    __shared__ float at[16][68];

    const int b = blockIdx.x;
    const int h = blockIdx.y;
    const int tid = threadIdx.x;

    // Load Q tile (16x64)
#pragma unroll
    for (int rep = 0; rep < 2; rep++) {
        const int uu = tid + rep * 128;
        const int i = uu >> 4, d4 = uu & 15;
        *(float4*)&qs[i][d4 * 4] =
            *(const float4*)(g_q + ((size_t)(b * 16 + i)) * 512 + h * 64 + d4 * 4);
    }
    // Load K,V tiles (64x64 each) from interleaved g_kv
#pragma unroll
    for (int rep = 0; rep < 8; rep++) {
        const int uu = tid + rep * 128;
        const int n = uu >> 4, d4 = uu & 15;
        const size_t base = ((size_t)(b * 64 + n)) * 1024 + h * 64 + d4 * 4;
        *(float4*)&ks[n][d4 * 4] = *(const float4*)(g_kv + base);
        *(float4*)&vs[n][d4 * 4] = *(const float4*)(g_kv + base + 512);
    }
    __syncthreads();

    const int i = tid >> 3;    // query row 0..15
    const int c = tid & 7;     // lane group 0..7
    const unsigned int* pm = pre_mask + ((size_t)b * 64 + i) * 64;  // word-per-bool

    // Logits for 8 key columns: n = c + j*8
    float lg[8];
    {
        float dacc[8] = {0,0,0,0,0,0,0,0};
        for (int d4 = 0; d4 < 16; d4++) {
            const float4 q = *(const float4*)&qs[i][d4 * 4];
#pragma unroll
            for (int j = 0; j < 8; j++) {
                const float4 kv = *(const float4*)&ks[c + j * 8][d4 * 4];
                dacc[j] = fmaf(q.x, kv.x, dacc[j]);
                dacc[j] = fmaf(q.y, kv.y, dacc[j]);
                dacc[j] = fmaf(q.z, kv.z, dacc[j]);
                dacc[j] = fmaf(q.w, kv.w, dacc[j]);
            }
        }
        const float NI = neg_inf();
        float mx = NI;
#pragma unroll
        for (int j = 0; j < 8; j++) {
            const int n = c + j * 8;
            lg[j] = (pm[n] != 0u) ? NI : dacc[j] * 0.125f;
            mx = fmaxf(mx, lg[j]);
        }
        // max over the 8 threads of this query row
        mx = fmaxf(mx, __shfl_xor_sync(0xffffffffu, mx, 1, 8));
        mx = fmaxf(mx, __shfl_xor_sync(0xffffffffu, mx, 2, 8));
        mx = fmaxf(mx, __shfl_xor_sync(0xffffffffu, mx, 4, 8));
        const bool any = (mx != NI);     // false -> all keys masked -> output 0
        float sum = 0.0f;
#pragma unroll
        for (int j = 0; j < 8; j++) {
            const float e = any ? __expf(lg[j] - mx) : 0.0f;  // exp(-inf)=0 for masked
            lg[j] = e;
            sum += e;
        }
        sum += __shfl_xor_sync(0xffffffffu, sum, 1, 8);
        sum += __shfl_xor_sync(0xffffffffu, sum, 2, 8);
        sum += __shfl_xor_sync(0xffffffffu, sum, 4, 8);
        const float inv = (sum > 0.0f) ? (1.0f / sum) : 0.0f;
#pragma unroll
        for (int j = 0; j < 8; j++)
            at[i][c + j * 8] = lg[j] * inv;
    }
    __syncthreads();

    // AV: thread owns contiguous d = c*8 .. c*8+7
    float4 o0 = make_float4(0,0,0,0), o1 = make_float4(0,0,0,0);
#pragma unroll 8
    for (int n = 0; n < 64; n++) {
        const float a = at[i][n];
        const float4 v0 = *(const float4*)&vs[n][c * 8];
        const float4 v1 = *(const float4*)&vs[n][c * 8 + 4];
        o0.x = fmaf(a, v0.x, o0.x); o0.y = fmaf(a, v0.y, o0.y);
        o0.z = fmaf(a, v0.z, o0.z); o0.w = fmaf(a, v0.w, o0.w);
        o1.x = fmaf(a, v1.x, o1.x); o1.y = fmaf(a, v1.y, o1.y);
        o1.z = fmaf(a, v1.z, o1.z); o1.w = fmaf(a, v1.w, o1.w);
    }
    float* outp = g_a + ((size_t)(b * 16 + i)) * 512 + h * 64 + c * 8;
    *(float4*)outp = o0;
    *(float4*)(outp + 4) = o1;
}

// ---------------------------------------------------------------------------
extern "C" void kernel_launch(void* const* d_in, const int* in_sizes, int n_in,
                              void* d_out, int out_size)
{
    const float*        entities  = (const float*)d_in[0];         // [2048,64,512]
    const unsigned int* pre_mask  = (const unsigned int*)d_in[1];  // [2048,64,64] bool->word
    const unsigned int* post_mask = (const unsigned int*)d_in[2];  // [2048,16]   bool->word
    const float*        W_in      = (const float*)d_in[3];         // [1536,512]
    const float*        W_out     = (const float*)d_in[4];         // [512,512]
    const float*        b_out     = (const float*)d_in[5];         // [512]
    float*              out       = (float*)d_out;                 // [2048,16,512]

    // KV projection: all 131072 entity rows x 1024 cols (W_in rows 512..1535)
    sgemm_kernel<0><<<dim3(8, 1024), 256>>>(entities, W_in + 512 * 512,
                                            nullptr, nullptr, nullptr);
    // Q projection: only rows n<16 per batch (32768 rows) x 512 cols
    sgemm_kernel<1><<<dim3(4, 256), 256>>>(entities, W_in,
                                           nullptr, nullptr, nullptr);
    // Fused attention per (batch, head)
    attn_kernel<<<dim3(BS, NHEAD), 128>>>(pre_mask);
    // Output projection + bias + post_mask
    sgemm_kernel<2><<<dim3(4, 256), 256>>>(nullptr, W_out, out, b_out, post_mask);
}

// round 5
// speedup vs baseline: 2.2677x; 2.2677x over previous
#include <cuda_runtime.h>
#include <cuda_bf16.h>
#include <math.h>
#include <stdint.h>

// Problem constants
#define BS      2048
#define NE      64
#define NQ      16
#define EMBED   512
#define NHEAD   8
#define HD      64

// ---------------------------------------------------------------------------
// Scratch (__device__ globals — allocation-free)
// ---------------------------------------------------------------------------
__device__ __nv_bfloat16 g_eh[(size_t)BS * NE * 512];   // entities hi
__device__ __nv_bfloat16 g_el[(size_t)BS * NE * 512];   // entities lo
__device__ __nv_bfloat16 g_wh[1536 * 512];              // W_in hi
__device__ __nv_bfloat16 g_wl[1536 * 512];              // W_in lo
__device__ __nv_bfloat16 g_oh[512 * 512];               // W_out hi
__device__ __nv_bfloat16 g_ol[512 * 512];               // W_out lo
__device__ float         g_q [(size_t)BS * NQ * 512];   // Q   fp32
__device__ float         g_kv[(size_t)BS * NE * 1024];  // K|V fp32
__device__ __nv_bfloat16 g_ah[(size_t)BS * NQ * 512];   // attn out hi
__device__ __nv_bfloat16 g_al[(size_t)BS * NQ * 512];   // attn out lo

__device__ __forceinline__ float neg_inf() { return __int_as_float(0xff800000u); }

__device__ __forceinline__ uint32_t smem_u32(const void* p) {
    uint32_t a;
    asm("{ .reg .u64 t; cvta.to.shared.u64 t, %1; cvt.u32.u64 %0, t; }" : "=r"(a) : "l"(p));
    return a;
}
#define SW128(bo) ((bo) ^ (((bo) >> 3) & 0x70))

#define CP_ASYNC16(dst, src) \
    asm volatile("cp.async.cg.shared.global [%0], [%1], 16;" :: "r"(dst), "l"(src) : "memory")
#define CP_COMMIT() asm volatile("cp.async.commit_group;" ::: "memory")
#define CP_WAIT1()  asm volatile("cp.async.wait_group 1;" ::: "memory")
#define CP_WAIT0()  asm volatile("cp.async.wait_group 0;" ::: "memory")

#define LDMATRIX_X4(r0, r1, r2, r3, addr) \
    asm volatile("ldmatrix.sync.aligned.m8n8.x4.shared.b16 {%0,%1,%2,%3}, [%4];" \
        : "=r"(r0), "=r"(r1), "=r"(r2), "=r"(r3) : "r"(addr))

#define MMA_BF16(c, a, b) \
    asm volatile("mma.sync.aligned.m16n8k16.row.col.f32.bf16.bf16.f32 " \
        "{%0,%1,%2,%3}, {%4,%5,%6,%7}, {%8,%9}, {%0,%1,%2,%3};" \
        : "+f"((c)[0]), "+f"((c)[1]), "+f"((c)[2]), "+f"((c)[3]) \
        : "r"((a)[0]), "r"((a)[1]), "r"((a)[2]), "r"((a)[3]), "r"((b)[0]), "r"((b)[1]))

// ---------------------------------------------------------------------------
// Split fp32 -> (bf16 hi, bf16 lo).  sel: 0=entities, 1=W_in, 2=W_out
// ---------------------------------------------------------------------------
__global__ void __launch_bounds__(256)
split_kernel(const float* __restrict__ src, int sel, int n4)
{
    __nv_bfloat16 *hi, *lo;
    if (sel == 0)      { hi = g_eh; lo = g_el; }
    else if (sel == 1) { hi = g_wh; lo = g_wl; }
    else               { hi = g_oh; lo = g_ol; }

    for (int i = blockIdx.x * blockDim.x + threadIdx.x; i < n4;
         i += gridDim.x * blockDim.x) {
        const float4 v = ((const float4*)src)[i];
        float f[4] = {v.x, v.y, v.z, v.w};
        unsigned short hs[4], ls[4];
#pragma unroll
        for (int j = 0; j < 4; j++) {
            __nv_bfloat16 hb = __float2bfloat16(f[j]);
            hs[j] = __bfloat16_as_ushort(hb);
            ls[j] = __bfloat16_as_ushort(__float2bfloat16(f[j] - __bfloat162float(hb)));
        }
        uint2 hv, lv;
        hv.x = (uint32_t)hs[0] | ((uint32_t)hs[1] << 16);
        hv.y = (uint32_t)hs[2] | ((uint32_t)hs[3] << 16);
        lv.x = (uint32_t)ls[0] | ((uint32_t)ls[1] << 16);
        lv.y = (uint32_t)ls[2] | ((uint32_t)ls[3] << 16);
        ((uint2*)hi)[i] = hv;
        ((uint2*)lo)[i] = lv;
    }
}

// ---------------------------------------------------------------------------
// mma.sync bf16x3 GEMM: C[m,n] = sum_d A[m,d]*B[n,d] with fp32 accumulate.
// CTA tile 128x256, 512 threads (16 warps: 2M x 8N), warp tile 64x32.
// BK=64 bf16 (128B rows, SW128-swizzled), double-buffered cp.async.
// Virtual K = 1536 (3 split terms x 512).
// MODE 0: KV proj (C=g_kv, ldc=1024)  MODE 1: Q proj (gathered A rows)
// MODE 2: out proj (bias + post_mask)
// ---------------------------------------------------------------------------
#define STAGE_BYTES 49152      // A 16KB + B 32KB
#define GSMEM_TOTAL (2 * STAGE_BYTES)
#define NITER 24

template <int MODE>
__global__ void __launch_bounds__(512, 1)
mma_gemm(float* __restrict__ Cout,
         const float* __restrict__ bias,
         const unsigned int* __restrict__ mask)
{
    extern __shared__ char smem[];
    const uint32_t sb = smem_u32(smem);
    const int tid  = threadIdx.x;
    const int wid  = tid >> 5;
    const int lane = tid & 31;
    const int wm   = wid & 1;          // 0..1  (M)
    const int wn   = wid >> 1;         // 0..7  (N)
    const int row0 = blockIdx.y * 128;
    const int col0 = blockIdx.x * 256;

    const __nv_bfloat16 *Ahp, *Alp, *Bhp, *Blp;
    if (MODE == 0)      { Ahp = g_eh; Alp = g_el; Bhp = g_wh + 512 * 512; Blp = g_wl + 512 * 512; }
    else if (MODE == 1) { Ahp = g_eh; Alp = g_el; Bhp = g_wh;             Blp = g_wl; }
    else                { Ahp = g_ah; Alp = g_al; Bhp = g_oh;             Blp = g_ol; }
    float* C = (MODE == 0) ? g_kv : (MODE == 1) ? g_q : Cout;
    const int ldc = (MODE == 0) ? 1024 : 512;

    float acc[4][4][4];
#pragma unroll
    for (int i = 0; i < 4; i++)
#pragma unroll
        for (int j = 0; j < 4; j++)
#pragma unroll
            for (int k = 0; k < 4; k++) acc[i][j][k] = 0.0f;

    // ---- async tile loader for virtual-K chunk t into stage s ----
    auto issue_load = [&](int t, int s) {
        const int term = t >> 3;                     // 0:AhBh 1:AhBl 2:AlBh
        const int kc   = (t & 7) * 64;
        const __nv_bfloat16* Asrc = (term < 2) ? Ahp : Alp;
        const __nv_bfloat16* Bsrc = (term == 1) ? Blp : Bhp;
        const uint32_t stA = sb + s * STAGE_BYTES;
        const uint32_t stB = stA + 16384;
#pragma unroll
        for (int i = 0; i < 2; i++) {                // A: 128 rows x 8 chunks
            const int u = tid + i * 512;
            const int r = u >> 3, c = u & 7;
            const int gr = row0 + r;
            const int ar = (MODE == 1) ? (((gr >> 4) << 6) + (gr & 15)) : gr;
            const __nv_bfloat16* src = Asrc + (size_t)ar * 512 + kc + c * 8;
            CP_ASYNC16(stA + SW128((uint32_t)(r * 128 + c * 16)), src);
        }
#pragma unroll
        for (int i = 0; i < 4; i++) {                // B: 256 rows x 8 chunks
            const int u = tid + i * 512;
            const int r = u >> 3, c = u & 7;
            const __nv_bfloat16* src = Bsrc + (size_t)(col0 + r) * 512 + kc + c * 8;
            CP_ASYNC16(stB + SW128((uint32_t)(r * 128 + c * 16)), src);
        }
        CP_COMMIT();
    };

    issue_load(0, 0);

    const int l8   = lane & 7;
    const int lsel = lane >> 3;                      // 0..3 (ldmatrix quad)

    for (int t = 0; t < NITER; t++) {
        const int s = t & 1;
        if (t + 1 < NITER) { issue_load(t + 1, s ^ 1); CP_WAIT1(); }
        else               { CP_WAIT0(); }
        __syncthreads();

        const uint32_t stA = sb + s * STAGE_BYTES;
        const uint32_t stB = stA + 16384;

#pragma unroll
        for (int ks = 0; ks < 4; ks++) {             // 4 x k16 per chunk
            // B fragments: 4 n8-tiles (2 x ldmatrix.x4 over n16k16)
            uint32_t b[4][2];
#pragma unroll
            for (int bp = 0; bp < 2; bp++) {
                const int rb = wn * 32 + bp * 16 + (lsel >> 1) * 8 + l8;
                const int cb = ks * 2 + (lsel & 1);
                const uint32_t ad = stB + (uint32_t)(rb * 128 + ((cb ^ (rb & 7)) << 4));
                LDMATRIX_X4(b[2 * bp][0], b[2 * bp][1], b[2 * bp + 1][0], b[2 * bp + 1][1], ad);
            }
#pragma unroll
            for (int am = 0; am < 4; am++) {
                const int ra = wm * 64 + am * 16 + l8 + (lsel & 1) * 8;
                const int ca = ks * 2 + (lsel >> 1);
                const uint32_t ad = stA + (uint32_t)(ra * 128 + ((ca ^ (ra & 7)) << 4));
                uint32_t a[4];
                LDMATRIX_X4(a[0], a[1], a[2], a[3], ad);
#pragma unroll
                for (int nt = 0; nt < 4; nt++)
                    MMA_BF16(acc[am][nt], a, b[nt]);
            }
        }
        __syncthreads();
    }

    // ---- epilogue: warp tile 64x32, frag (g,tg) layout ----
    const int g  = lane >> 2;
    const int tg = lane & 3;
#pragma unroll
    for (int am = 0; am < 4; am++) {
        const int r0 = row0 + wm * 64 + am * 16 + g;
        const int r1 = r0 + 8;
        bool z0 = false, z1 = false;
        if (MODE == 2) { z0 = (mask[r0] != 0u); z1 = (mask[r1] != 0u); }
#pragma unroll
        for (int nt = 0; nt < 4; nt++) {
            const int col = col0 + wn * 32 + nt * 8 + tg * 2;
            float2 v0 = make_float2(acc[am][nt][0], acc[am][nt][1]);
            float2 v1 = make_float2(acc[am][nt][2], acc[am][nt][3]);
            if (MODE == 2) {
                const float bb0 = bias[col], bb1 = bias[col + 1];
                v0.x = z0 ? 0.0f : v0.x + bb0;  v0.y = z0 ? 0.0f : v0.y + bb1;
                v1.x = z1 ? 0.0f : v1.x + bb0;  v1.y = z1 ? 0.0f : v1.y + bb1;
            }
            *(float2*)(C + (size_t)r0 * ldc + col) = v0;
            *(float2*)(C + (size_t)r1 * ldc + col) = v1;
        }
    }
}

// ---------------------------------------------------------------------------
// Attention: one block per (batch, head). 128 threads. Emits bf16 hi/lo.
// ---------------------------------------------------------------------------
__global__ void __launch_bounds__(128)
attn_kernel(const unsigned int* __restrict__ pre_mask)
{
    __shared__ float qs[16][68];
    __shared__ float ks[64][68];
    __shared__ float vs[64][68];
    __shared__ float at[16][68];

    const int b = blockIdx.x;
    const int h = blockIdx.y;
    const int tid = threadIdx.x;

#pragma unroll
    for (int rep = 0; rep < 2; rep++) {
        const int uu = tid + rep * 128;
        const int i = uu >> 4, d4 = uu & 15;
        *(float4*)&qs[i][d4 * 4] =
            *(const float4*)(g_q + ((size_t)(b * 16 + i)) * 512 + h * 64 + d4 * 4);
    }
#pragma unroll
    for (int rep = 0; rep < 8; rep++) {
        const int uu = tid + rep * 128;
        const int n = uu >> 4, d4 = uu & 15;
        const size_t base = ((size_t)(b * 64 + n)) * 1024 + h * 64 + d4 * 4;
        *(float4*)&ks[n][d4 * 4] = *(const float4*)(g_kv + base);
        *(float4*)&vs[n][d4 * 4] = *(const float4*)(g_kv + base + 512);
    }
    __syncthreads();

    const int i = tid >> 3;
    const int c = tid & 7;
    const unsigned int* pm = pre_mask + ((size_t)b * 64 + i) * 64;

    float lg[8];
    {
        float dacc[8] = {0, 0, 0, 0, 0, 0, 0, 0};
        for (int d4 = 0; d4 < 16; d4++) {
            const float4 q = *(const float4*)&qs[i][d4 * 4];
#pragma unroll
            for (int j = 0; j < 8; j++) {
                const float4 kv = *(const float4*)&ks[c + j * 8][d4 * 4];
                dacc[j] = fmaf(q.x, kv.x, dacc[j]);
                dacc[j] = fmaf(q.y, kv.y, dacc[j]);
                dacc[j] = fmaf(q.z, kv.z, dacc[j]);
                dacc[j] = fmaf(q.w, kv.w, dacc[j]);
            }
        }
        const float NI = neg_inf();
        float mx = NI;
#pragma unroll
        for (int j = 0; j < 8; j++) {
            lg[j] = (pm[c + j * 8] != 0u) ? NI : dacc[j] * 0.125f;
            mx = fmaxf(mx, lg[j]);
        }
        mx = fmaxf(mx, __shfl_xor_sync(0xffffffffu, mx, 1, 8));
        mx = fmaxf(mx, __shfl_xor_sync(0xffffffffu, mx, 2, 8));
        mx = fmaxf(mx, __shfl_xor_sync(0xffffffffu, mx, 4, 8));
        const bool any = (mx != NI);
        float sum = 0.0f;
#pragma unroll
        for (int j = 0; j < 8; j++) {
            const float e = any ? __expf(lg[j] - mx) : 0.0f;
            lg[j] = e;
            sum += e;
        }
        sum += __shfl_xor_sync(0xffffffffu, sum, 1, 8);
        sum += __shfl_xor_sync(0xffffffffu, sum, 2, 8);
        sum += __shfl_xor_sync(0xffffffffu, sum, 4, 8);
        const float inv = (sum > 0.0f) ? (1.0f / sum) : 0.0f;
#pragma unroll
        for (int j = 0; j < 8; j++)
            at[i][c + j * 8] = lg[j] * inv;
    }
    __syncthreads();

    float4 o0 = make_float4(0, 0, 0, 0), o1 = make_float4(0, 0, 0, 0);
#pragma unroll 8
    for (int n = 0; n < 64; n++) {
        const float a = at[i][n];
        const float4 v0 = *(const float4*)&vs[n][c * 8];
        const float4 v1 = *(const float4*)&vs[n][c * 8 + 4];
        o0.x = fmaf(a, v0.x, o0.x); o0.y = fmaf(a, v0.y, o0.y);
        o0.z = fmaf(a, v0.z, o0.z); o0.w = fmaf(a, v0.w, o0.w);
        o1.x = fmaf(a, v1.x, o1.x); o1.y = fmaf(a, v1.y, o1.y);
        o1.z = fmaf(a, v1.z, o1.z); o1.w = fmaf(a, v1.w, o1.w);
    }
    float ov[8] = {o0.x, o0.y, o0.z, o0.w, o1.x, o1.y, o1.z, o1.w};
    unsigned short hs[8], ls[8];
#pragma unroll
    for (int j = 0; j < 8; j++) {
        __nv_bfloat16 hb = __float2bfloat16(ov[j]);
        hs[j] = __bfloat16_as_ushort(hb);
        ls[j] = __bfloat16_as_ushort(__float2bfloat16(ov[j] - __bfloat162float(hb)));
    }
    uint4 hv, lv;
    hv.x = (uint32_t)hs[0] | ((uint32_t)hs[1] << 16);
    hv.y = (uint32_t)hs[2] | ((uint32_t)hs[3] << 16);
    hv.z = (uint32_t)hs[4] | ((uint32_t)hs[5] << 16);
    hv.w = (uint32_t)hs[6] | ((uint32_t)hs[7] << 16);
    lv.x = (uint32_t)ls[0] | ((uint32_t)ls[1] << 16);
    lv.y = (uint32_t)ls[2] | ((uint32_t)ls[3] << 16);
    lv.z = (uint32_t)ls[4] | ((uint32_t)ls[5] << 16);
    lv.w = (uint32_t)ls[6] | ((uint32_t)ls[7] << 16);
    const size_t base = ((size_t)(b * 16 + i)) * 512 + h * 64 + c * 8;
    *(uint4*)(g_ah + base) = hv;
    *(uint4*)(g_al + base) = lv;
}

// ---------------------------------------------------------------------------
extern "C" void kernel_launch(void* const* d_in, const int* in_sizes, int n_in,
                              void* d_out, int out_size)
{
    const float*        entities  = (const float*)d_in[0];
    const unsigned int* pre_mask  = (const unsigned int*)d_in[1];
    const unsigned int* post_mask = (const unsigned int*)d_in[2];
    const float*        W_in      = (const float*)d_in[3];
    const float*        W_out     = (const float*)d_in[4];
    const float*        b_out     = (const float*)d_in[5];
    float*              out       = (float*)d_out;

    cudaFuncSetAttribute(mma_gemm<0>, cudaFuncAttributeMaxDynamicSharedMemorySize, GSMEM_TOTAL);
    cudaFuncSetAttribute(mma_gemm<1>, cudaFuncAttributeMaxDynamicSharedMemorySize, GSMEM_TOTAL);
    cudaFuncSetAttribute(mma_gemm<2>, cudaFuncAttributeMaxDynamicSharedMemorySize, GSMEM_TOTAL);

    // hi/lo splits
    split_kernel<<<8192, 256>>>(entities, 0, (BS * NE * 512) / 4);
    split_kernel<<<768,  256>>>(W_in,     1, (1536 * 512) / 4);
    split_kernel<<<256,  256>>>(W_out,    2, (512 * 512) / 4);

    // KV projection: M=131072, N=1024
    mma_gemm<0><<<dim3(4, 1024), 512, GSMEM_TOTAL>>>(nullptr, nullptr, nullptr);
    // Q projection: M=32768 (gathered rows), N=512
    mma_gemm<1><<<dim3(2, 256), 512, GSMEM_TOTAL>>>(nullptr, nullptr, nullptr);
    // Attention
    attn_kernel<<<dim3(BS, NHEAD), 128>>>(pre_mask);
    // Output projection + bias + post_mask
    mma_gemm<2><<<dim3(2, 256), 512, GSMEM_TOTAL>>>(out, b_out, post_mask);
}

// round 6
// speedup vs baseline: 2.5310x; 1.1161x over previous
#include <cuda_runtime.h>
#include <cuda_bf16.h>
#include <math.h>
#include <stdint.h>

// Problem constants
#define BS      2048
#define NE      64
#define NQ      16
#define EMBED   512
#define NHEAD   8
#define HD      64

// ---------------------------------------------------------------------------
// Scratch (__device__ globals — allocation-free)
// ---------------------------------------------------------------------------
__device__ __nv_bfloat16 g_eh[(size_t)BS * NE * 512];   // entities hi
__device__ __nv_bfloat16 g_el[(size_t)BS * NE * 512];   // entities lo
__device__ __nv_bfloat16 g_wh[1536 * 512];              // W_in hi
__device__ __nv_bfloat16 g_wl[1536 * 512];              // W_in lo
__device__ __nv_bfloat16 g_oh[512 * 512];               // W_out hi
__device__ __nv_bfloat16 g_ol[512 * 512];               // W_out lo
__device__ float         g_q [(size_t)BS * NQ * 512];   // Q   fp32
__device__ float         g_kv[(size_t)BS * NE * 1024];  // K|V fp32
__device__ __nv_bfloat16 g_ah[(size_t)BS * NQ * 512];   // attn out hi
__device__ __nv_bfloat16 g_al[(size_t)BS * NQ * 512];   // attn out lo

__device__ __forceinline__ float neg_inf() { return __int_as_float(0xff800000u); }

__device__ __forceinline__ uint32_t smem_u32(const void* p) {
    uint32_t a;
    asm("{ .reg .u64 t; cvta.to.shared.u64 t, %1; cvt.u32.u64 %0, t; }" : "=r"(a) : "l"(p));
    return a;
}
#define SW128(bo) ((bo) ^ (((bo) >> 3) & 0x70))

#define CP_ASYNC16(dst, src) \
    asm volatile("cp.async.cg.shared.global [%0], [%1], 16;" :: "r"(dst), "l"(src) : "memory")
#define CP_COMMIT() asm volatile("cp.async.commit_group;" ::: "memory")
#define CP_WAIT1()  asm volatile("cp.async.wait_group 1;" ::: "memory")
#define CP_WAIT0()  asm volatile("cp.async.wait_group 0;" ::: "memory")

#define LDMATRIX_X4(r0, r1, r2, r3, addr) \
    asm volatile("ldmatrix.sync.aligned.m8n8.x4.shared.b16 {%0,%1,%2,%3}, [%4];" \
        : "=r"(r0), "=r"(r1), "=r"(r2), "=r"(r3) : "r"(addr))

#define MMA_BF16(c, a, b) \
    asm volatile("mma.sync.aligned.m16n8k16.row.col.f32.bf16.bf16.f32 " \
        "{%0,%1,%2,%3}, {%4,%5,%6,%7}, {%8,%9}, {%0,%1,%2,%3};" \
        : "+f"((c)[0]), "+f"((c)[1]), "+f"((c)[2]), "+f"((c)[3]) \
        : "r"((a)[0]), "r"((a)[1]), "r"((a)[2]), "r"((a)[3]), "r"((b)[0]), "r"((b)[1]))

// ---------------------------------------------------------------------------
// Split fp32 -> (bf16 hi, bf16 lo).  sel: 0=entities, 1=W_in, 2=W_out
// ---------------------------------------------------------------------------
__global__ void __launch_bounds__(256)
split_kernel(const float* __restrict__ src, int sel, int n4)
{
    __nv_bfloat16 *hi, *lo;
    if (sel == 0)      { hi = g_eh; lo = g_el; }
    else if (sel == 1) { hi = g_wh; lo = g_wl; }
    else               { hi = g_oh; lo = g_ol; }

    for (int i = blockIdx.x * blockDim.x + threadIdx.x; i < n4;
         i += gridDim.x * blockDim.x) {
        const float4 v = ((const float4*)src)[i];
        float f[4] = {v.x, v.y, v.z, v.w};
        unsigned short hs[4], ls[4];
#pragma unroll
        for (int j = 0; j < 4; j++) {
            __nv_bfloat16 hb = __float2bfloat16(f[j]);
            hs[j] = __bfloat16_as_ushort(hb);
            ls[j] = __bfloat16_as_ushort(__float2bfloat16(f[j] - __bfloat162float(hb)));
        }
        uint2 hv, lv;
        hv.x = (uint32_t)hs[0] | ((uint32_t)hs[1] << 16);
        hv.y = (uint32_t)hs[2] | ((uint32_t)hs[3] << 16);
        lv.x = (uint32_t)ls[0] | ((uint32_t)ls[1] << 16);
        lv.y = (uint32_t)ls[2] | ((uint32_t)ls[3] << 16);
        ((uint2*)hi)[i] = hv;
        ((uint2*)lo)[i] = lv;
    }
}

// ---------------------------------------------------------------------------
// mma.sync bf16x3 GEMM with operand reuse:
// C[m,n] = sum_d A[m,d]*B[n,d], terms Ah*Bh + Ah*Bl + Al*Bh (fp32 accum).
// CTA tile 128x256, 512 threads (16 warps: 2M x 8N), warp tile 64x32.
// Per k-chunk (BK=64) load Ah|Al|Bh|Bl (96KB/stage, 2 stages = 192KB smem),
// compute all 3 terms from one residency. 8 chunks total.
// MODE 0: KV proj (C=g_kv, ldc=1024)  MODE 1: Q proj (gathered A rows)
// MODE 2: out proj (bias + post_mask)
// ---------------------------------------------------------------------------
#define STAGE_BYTES 98304      // Ah 16K | Al 16K | Bh 32K | Bl 32K
#define OFF_AL      16384
#define OFF_BH      32768
#define OFF_BL      65536
#define GSMEM_TOTAL (2 * STAGE_BYTES)
#define NITER 8

template <int MODE>
__global__ void __launch_bounds__(512, 1)
mma_gemm(float* __restrict__ Cout,
         const float* __restrict__ bias,
         const unsigned int* __restrict__ mask)
{
    extern __shared__ char smem[];
    const uint32_t sb = smem_u32(smem);
    const int tid  = threadIdx.x;
    const int wid  = tid >> 5;
    const int lane = tid & 31;
    const int wm   = wid & 1;          // 0..1  (M)
    const int wn   = wid >> 1;         // 0..7  (N)
    const int row0 = blockIdx.y * 128;
    const int col0 = blockIdx.x * 256;

    const __nv_bfloat16 *Ahp, *Alp, *Bhp, *Blp;
    if (MODE == 0)      { Ahp = g_eh; Alp = g_el; Bhp = g_wh + 512 * 512; Blp = g_wl + 512 * 512; }
    else if (MODE == 1) { Ahp = g_eh; Alp = g_el; Bhp = g_wh;             Blp = g_wl; }
    else                { Ahp = g_ah; Alp = g_al; Bhp = g_oh;             Blp = g_ol; }
    float* C = (MODE == 0) ? g_kv : (MODE == 1) ? g_q : Cout;
    const int ldc = (MODE == 0) ? 1024 : 512;

    float acc[4][4][4];
#pragma unroll
    for (int i = 0; i < 4; i++)
#pragma unroll
        for (int j = 0; j < 4; j++)
#pragma unroll
            for (int k = 0; k < 4; k++) acc[i][j][k] = 0.0f;

    // ---- async loader: all four operand tiles of k-chunk t into stage s ----
    auto issue_load = [&](int t, int s) {
        const int kc = t * 64;
        const uint32_t st = sb + s * STAGE_BYTES;
#pragma unroll
        for (int i = 0; i < 2; i++) {                // Ah, Al: 128 rows x 8 chunks
            const int u = tid + i * 512;
            const int r = u >> 3, c = u & 7;
            const int gr = row0 + r;
            const int ar = (MODE == 1) ? (((gr >> 4) << 6) + (gr & 15)) : gr;
            const uint32_t sw = SW128((uint32_t)(r * 128 + c * 16));
            CP_ASYNC16(st + sw,          Ahp + (size_t)ar * 512 + kc + c * 8);
            CP_ASYNC16(st + OFF_AL + sw, Alp + (size_t)ar * 512 + kc + c * 8);
        }
#pragma unroll
        for (int i = 0; i < 4; i++) {                // Bh, Bl: 256 rows x 8 chunks
            const int u = tid + i * 512;
            const int r = u >> 3, c = u & 7;
            const uint32_t sw = SW128((uint32_t)(r * 128 + c * 16));
            CP_ASYNC16(st + OFF_BH + sw, Bhp + (size_t)(col0 + r) * 512 + kc + c * 8);
            CP_ASYNC16(st + OFF_BL + sw, Blp + (size_t)(col0 + r) * 512 + kc + c * 8);
        }
        CP_COMMIT();
    };

    issue_load(0, 0);

    const int l8   = lane & 7;
    const int lsel = lane >> 3;                      // 0..3 (ldmatrix quad)

    for (int t = 0; t < NITER; t++) {
        const int s = t & 1;
        if (t + 1 < NITER) { issue_load(t + 1, s ^ 1); CP_WAIT1(); }
        else               { CP_WAIT0(); }
        __syncthreads();

        const uint32_t st = sb + s * STAGE_BYTES;

#pragma unroll
        for (int ks = 0; ks < 4; ks++) {             // 4 x k16 per chunk
            // fragment smem addresses (shared across hi/lo: same layout)
            const int ra = wm * 64 + l8 + (lsel & 1) * 8;
            const int ca = ks * 2 + (lsel >> 1);
            const int rb = wn * 32 + (lsel >> 1) * 8 + l8;
            const int cb = ks * 2 + (lsel & 1);

            uint32_t ah[4][4], al[4][4], bh[4][2], bl[4][2];
#pragma unroll
            for (int am = 0; am < 4; am++) {
                const int r = ra + am * 16;
                const uint32_t off = (uint32_t)(r * 128 + ((ca ^ (r & 7)) << 4));
                LDMATRIX_X4(ah[am][0], ah[am][1], ah[am][2], ah[am][3], st + off);
            }
#pragma unroll
            for (int bp = 0; bp < 2; bp++) {
                const int r = rb + bp * 16;
                const uint32_t off = (uint32_t)(r * 128 + ((cb ^ (r & 7)) << 4));
                LDMATRIX_X4(bh[2 * bp][0], bh[2 * bp][1], bh[2 * bp + 1][0], bh[2 * bp + 1][1],
                            st + OFF_BH + off);
            }
            // term 0: Ah * Bh
#pragma unroll
            for (int am = 0; am < 4; am++)
#pragma unroll
                for (int nt = 0; nt < 4; nt++)
                    MMA_BF16(acc[am][nt], ah[am], bh[nt]);
            // term 1: Ah * Bl
#pragma unroll
            for (int bp = 0; bp < 2; bp++) {
                const int r = rb + bp * 16;
                const uint32_t off = (uint32_t)(r * 128 + ((cb ^ (r & 7)) << 4));
                LDMATRIX_X4(bl[2 * bp][0], bl[2 * bp][1], bl[2 * bp + 1][0], bl[2 * bp + 1][1],
                            st + OFF_BL + off);
            }
#pragma unroll
            for (int am = 0; am < 4; am++)
#pragma unroll
                for (int nt = 0; nt < 4; nt++)
                    MMA_BF16(acc[am][nt], ah[am], bl[nt]);
            // term 2: Al * Bh
#pragma unroll
            for (int am = 0; am < 4; am++) {
                const int r = ra + am * 16;
                const uint32_t off = (uint32_t)(r * 128 + ((ca ^ (r & 7)) << 4));
                LDMATRIX_X4(al[am][0], al[am][1], al[am][2], al[am][3], st + OFF_AL + off);
            }
#pragma unroll
            for (int am = 0; am < 4; am++)
#pragma unroll
                for (int nt = 0; nt < 4; nt++)
                    MMA_BF16(acc[am][nt], al[am], bh[nt]);
        }
        __syncthreads();
    }

    // ---- epilogue: warp tile 64x32, frag (g,tg) layout ----
    const int g  = lane >> 2;
    const int tg = lane & 3;
#pragma unroll
    for (int am = 0; am < 4; am++) {
        const int r0 = row0 + wm * 64 + am * 16 + g;
        const int r1 = r0 + 8;
        bool z0 = false, z1 = false;
        if (MODE == 2) { z0 = (mask[r0] != 0u); z1 = (mask[r1] != 0u); }
#pragma unroll
        for (int nt = 0; nt < 4; nt++) {
            const int col = col0 + wn * 32 + nt * 8 + tg * 2;
            float2 v0 = make_float2(acc[am][nt][0], acc[am][nt][1]);
            float2 v1 = make_float2(acc[am][nt][2], acc[am][nt][3]);
            if (MODE == 2) {
                const float bb0 = bias[col], bb1 = bias[col + 1];
                v0.x = z0 ? 0.0f : v0.x + bb0;  v0.y = z0 ? 0.0f : v0.y + bb1;
                v1.x = z1 ? 0.0f : v1.x + bb0;  v1.y = z1 ? 0.0f : v1.y + bb1;
            }
            *(float2*)(C + (size_t)r0 * ldc + col) = v0;
            *(float2*)(C + (size_t)r1 * ldc + col) = v1;
        }
    }
}

// ---------------------------------------------------------------------------
// Attention: one block per (batch, head). 128 threads. Emits bf16 hi/lo.
// ---------------------------------------------------------------------------
__global__ void __launch_bounds__(128)
attn_kernel(const unsigned int* __restrict__ pre_mask)
{
    __shared__ float qs[16][68];
    __shared__ float ks[64][68];
    __shared__ float vs[64][68];
    __shared__ float at[16][68];

    const int b = blockIdx.x;
    const int h = blockIdx.y;
    const int tid = threadIdx.x;

#pragma unroll
    for (int rep = 0; rep < 2; rep++) {
        const int uu = tid + rep * 128;
        const int i = uu >> 4, d4 = uu & 15;
        *(float4*)&qs[i][d4 * 4] =
            *(const float4*)(g_q + ((size_t)(b * 16 + i)) * 512 + h * 64 + d4 * 4);
    }
#pragma unroll
    for (int rep = 0; rep < 8; rep++) {
        const int uu = tid + rep * 128;
        const int n = uu >> 4, d4 = uu & 15;
        const size_t base = ((size_t)(b * 64 + n)) * 1024 + h * 64 + d4 * 4;
        *(float4*)&ks[n][d4 * 4] = *(const float4*)(g_kv + base);
        *(float4*)&vs[n][d4 * 4] = *(const float4*)(g_kv + base + 512);
    }
    __syncthreads();

    const int i = tid >> 3;
    const int c = tid & 7;
    const unsigned int* pm = pre_mask + ((size_t)b * 64 + i) * 64;

    float lg[8];
    {
        float dacc[8] = {0, 0, 0, 0, 0, 0, 0, 0};
        for (int d4 = 0; d4 < 16; d4++) {
            const float4 q = *(const float4*)&qs[i][d4 * 4];
#pragma unroll
            for (int j = 0; j < 8; j++) {
                const float4 kv = *(const float4*)&ks[c + j * 8][d4 * 4];
                dacc[j] = fmaf(q.x, kv.x, dacc[j]);
                dacc[j] = fmaf(q.y, kv.y, dacc[j]);
                dacc[j] = fmaf(q.z, kv.z, dacc[j]);
                dacc[j] = fmaf(q.w, kv.w, dacc[j]);
            }
        }
        const float NI = neg_inf();
        float mx = NI;
#pragma unroll
        for (int j = 0; j < 8; j++) {
            lg[j] = (pm[c + j * 8] != 0u) ? NI : dacc[j] * 0.125f;
            mx = fmaxf(mx, lg[j]);
        }
        mx = fmaxf(mx, __shfl_xor_sync(0xffffffffu, mx, 1, 8));
        mx = fmaxf(mx, __shfl_xor_sync(0xffffffffu, mx, 2, 8));
        mx = fmaxf(mx, __shfl_xor_sync(0xffffffffu, mx, 4, 8));
        const bool any = (mx != NI);
        float sum = 0.0f;
#pragma unroll
        for (int j = 0; j < 8; j++) {
            const float e = any ? __expf(lg[j] - mx) : 0.0f;
            lg[j] = e;
            sum += e;
        }
        sum += __shfl_xor_sync(0xffffffffu, sum, 1, 8);
        sum += __shfl_xor_sync(0xffffffffu, sum, 2, 8);
        sum += __shfl_xor_sync(0xffffffffu, sum, 4, 8);
        const float inv = (sum > 0.0f) ? (1.0f / sum) : 0.0f;
#pragma unroll
        for (int j = 0; j < 8; j++)
            at[i][c + j * 8] = lg[j] * inv;
    }
    __syncthreads();

    float4 o0 = make_float4(0, 0, 0, 0), o1 = make_float4(0, 0, 0, 0);
#pragma unroll 8
    for (int n = 0; n < 64; n++) {
        const float a = at[i][n];
        const float4 v0 = *(const float4*)&vs[n][c * 8];
        const float4 v1 = *(const float4*)&vs[n][c * 8 + 4];
        o0.x = fmaf(a, v0.x, o0.x); o0.y = fmaf(a, v0.y, o0.y);
        o0.z = fmaf(a, v0.z, o0.z); o0.w = fmaf(a, v0.w, o0.w);
        o1.x = fmaf(a, v1.x, o1.x); o1.y = fmaf(a, v1.y, o1.y);
        o1.z = fmaf(a, v1.z, o1.z); o1.w = fmaf(a, v1.w, o1.w);
    }
    float ov[8] = {o0.x, o0.y, o0.z, o0.w, o1.x, o1.y, o1.z, o1.w};
    unsigned short hs[8], ls[8];
#pragma unroll
    for (int j = 0; j < 8; j++) {
        __nv_bfloat16 hb = __float2bfloat16(ov[j]);
        hs[j] = __bfloat16_as_ushort(hb);
        ls[j] = __bfloat16_as_ushort(__float2bfloat16(ov[j] - __bfloat162float(hb)));
    }
    uint4 hv, lv;
    hv.x = (uint32_t)hs[0] | ((uint32_t)hs[1] << 16);
    hv.y = (uint32_t)hs[2] | ((uint32_t)hs[3] << 16);
    hv.z = (uint32_t)hs[4] | ((uint32_t)hs[5] << 16);
    hv.w = (uint32_t)hs[6] | ((uint32_t)hs[7] << 16);
    lv.x = (uint32_t)ls[0] | ((uint32_t)ls[1] << 16);
    lv.y = (uint32_t)ls[2] | ((uint32_t)ls[3] << 16);
    lv.z = (uint32_t)ls[4] | ((uint32_t)ls[5] << 16);
    lv.w = (uint32_t)ls[6] | ((uint32_t)ls[7] << 16);
    const size_t base = ((size_t)(b * 16 + i)) * 512 + h * 64 + c * 8;
    *(uint4*)(g_ah + base) = hv;
    *(uint4*)(g_al + base) = lv;
}

// ---------------------------------------------------------------------------
extern "C" void kernel_launch(void* const* d_in, const int* in_sizes, int n_in,
                              void* d_out, int out_size)
{
    const float*        entities  = (const float*)d_in[0];
    const unsigned int* pre_mask  = (const unsigned int*)d_in[1];
    const unsigned int* post_mask = (const unsigned int*)d_in[2];
    const float*        W_in      = (const float*)d_in[3];
    const float*        W_out     = (const float*)d_in[4];
    const float*        b_out     = (const float*)d_in[5];
    float*              out       = (float*)d_out;

    cudaFuncSetAttribute(mma_gemm<0>, cudaFuncAttributeMaxDynamicSharedMemorySize, GSMEM_TOTAL);
    cudaFuncSetAttribute(mma_gemm<1>, cudaFuncAttributeMaxDynamicSharedMemorySize, GSMEM_TOTAL);
    cudaFuncSetAttribute(mma_gemm<2>, cudaFuncAttributeMaxDynamicSharedMemorySize, GSMEM_TOTAL);

    // hi/lo splits
    split_kernel<<<8192, 256>>>(entities, 0, (BS * NE * 512) / 4);
    split_kernel<<<768,  256>>>(W_in,     1, (1536 * 512) / 4);
    split_kernel<<<256,  256>>>(W_out,    2, (512 * 512) / 4);

    // KV projection: M=131072, N=1024
    mma_gemm<0><<<dim3(4, 1024), 512, GSMEM_TOTAL>>>(nullptr, nullptr, nullptr);
    // Q projection: M=32768 (gathered rows), N=512
    mma_gemm<1><<<dim3(2, 256), 512, GSMEM_TOTAL>>>(nullptr, nullptr, nullptr);
    // Attention
    attn_kernel<<<dim3(BS, NHEAD), 128>>>(pre_mask);
    // Output projection + bias + post_mask
    mma_gemm<2><<<dim3(2, 256), 512, GSMEM_TOTAL>>>(out, b_out, post_mask);
}